// round 1
// baseline (speedup 1.0000x reference)
#include <cuda_runtime.h>
#include <math.h>

// Problem constants
#define HD   96
#define WD   96
#define NB   4
#define NT0  4
#define NT1  8
#define NZ   32
// tile
#define PXB  32     // pixels (w) per block
#define NWARPS 8
#define PXW  4      // pixels per warp

// shared layout (floats)
#define IN_SH_F   (128*181)          // 23168 : in_sh[ch][y*36+x], ch-stride 181 (5*36+1 pad)
#define CONV_SH_F (NWARPS*32*33)     // 8448  : per-warp conv[zz][o*8+j], zz-stride 33
#define OUT_SH_F  (256*33)           // 8448  : out[(t*32+z)][px], row-stride 33
#define WC_SH_F   800
#define MP_SH_F   512
#define MA_SH_F   512
#define BA_SH_F   32
#define SMEM_F (IN_SH_F + CONV_SH_F + OUT_SH_F + WC_SH_F + MP_SH_F + MA_SH_F + BA_SH_F)

__global__ void __launch_bounds__(256, 1)
caps2d_fused_kernel(const float* __restrict__ inp,
                    const float* __restrict__ Wc,
                    const float* __restrict__ Wp,
                    const float* __restrict__ Wa,
                    const float* __restrict__ ba,
                    float* __restrict__ out)
{
    extern __shared__ float smem[];
    float* in_sh   = smem;
    float* conv_sh = in_sh + IN_SH_F;
    float* out_sh  = conv_sh + CONV_SH_F;
    float* wc_sh   = out_sh + OUT_SH_F;
    float* mp_sh   = wc_sh + WC_SH_F;
    float* ma_sh   = mp_sh + MP_SH_F;
    float* ba_sh   = ma_sh + MA_SH_F;

    const int tid  = threadIdx.x;
    const int warp = tid >> 5;
    const int lane = tid & 31;
    const int w0   = blockIdx.x * PXB;
    const int hh   = blockIdx.y;
    const int n    = blockIdx.z;

    // ---- load small weights ----
    for (int e = tid; e < WC_SH_F; e += 256) wc_sh[e] = Wc[e];
    for (int e = tid; e < 512; e += 256) {
        int o = e >> 7, r = e & 127, t = r >> 4, b = r & 3;
        // column norm of W_pos[o] over k (axis=-2) for fixed (t,b)
        float s = 0.f;
        #pragma unroll
        for (int kk = 0; kk < 4; kk++) {
            float v = Wp[o*128 + t*16 + kk*4 + b];
            s += v * v;
        }
        float nrm = sqrtf(fmaxf(s, 1e-12f));
        mp_sh[e] = Wp[e] / nrm;   // e == o*128 + t*16 + k*4 + b
        ma_sh[e] = Wa[e];
    }
    if (tid < 32) ba_sh[tid] = ba[tid];

    // ---- load input halo tile: ch in [0,128), y in [0,5), x in [0,36) ----
    for (int e = tid; e < 128*180; e += 256) {
        int ch = e / 180;
        int r  = e - ch * 180;
        int y  = r / 36;
        int x  = r - y * 36;
        int gy = hh + y - 2;
        int gx = w0 + x - 2;
        float v = 0.f;
        if (gy >= 0 && gy < HD && gx >= 0 && gx < WD)
            v = inp[((n*128 + ch)*HD + gy)*WD + gx];
        in_sh[ch*181 + y*36 + x] = v;
    }
    __syncthreads();

    const int a_  = (lane >> 2) & 3;   // pose/app matrix row
    const int bb  = lane & 3;          // pose/app matrix col
    const int app = lane >> 4;         // 0 = pos half (z<16), 1 = app half
    float* csh = conv_sh + warp * (32*33);

    const float cw  = (float)0 ;  // placeholder (avoid unused warnings pattern)
    (void)cw;

    for (int ip = 0; ip < PXW; ip++) {
        const int p  = warp * PXW + ip;
        const int gw = w0 + p;

        // ---- phase 1: depthwise 5x5 conv for zz = lane, all o, 8 filters ----
        __syncwarp();
        {
            float acc[32];
            #pragma unroll
            for (int q = 0; q < 32; q++) acc[q] = 0.f;
            #pragma unroll
            for (int o = 0; o < 4; o++) {
                const float* ib = in_sh + (o*32 + lane)*181;
                #pragma unroll
                for (int ky = 0; ky < 5; ky++) {
                    #pragma unroll
                    for (int kx = 0; kx < 5; kx++) {
                        float v = ib[ky*36 + p + kx];
                        const float* wr = wc_sh + ((o*5 + ky)*5 + kx)*8;
                        #pragma unroll
                        for (int j = 0; j < 8; j++)
                            acc[o*8 + j] = fmaf(v, wr[j], acc[o*8 + j]);
                    }
                }
            }
            #pragma unroll
            for (int q = 0; q < 32; q++) csh[lane*33 + q] = acc[q];
        }
        __syncwarp();

        // ---- phase 2: u_hat[z=lane][o][t] ----
        float uh[32];
        const float cx = (float)gw * (1.f/96.f);
        const float cy = (float)hh * (1.f/96.f);
        #pragma unroll
        for (int o = 0; o < 4; o++) {
            #pragma unroll
            for (int t = 0; t < 8; t++) {
                const int j    = (app ? 4 : 0) + (t >> 1);
                const int zb   = ((t & 1) << 4) + (a_ << 2);
                const float bias = app ? ba_sh[o*8 + t] : 0.f;
                float s = 0.f;
                #pragma unroll
                for (int k = 0; k < 4; k++) {
                    float c = csh[(zb + k)*33 + o*8 + j] + bias;
                    float m;
                    if (app) {
                        m = ma_sh[o*128 + t*16 + k*4 + bb];
                    } else {
                        m = mp_sh[o*128 + t*16 + k*4 + bb];
                        if (k == 3) {
                            if (bb == 0)      m += cx;
                            else if (bb == 1) m += cy;
                        }
                    }
                    s = fmaf(c, m, s);
                }
                uh[o*8 + t] = s;
            }
        }

        // ---- phase 3: dynamic routing (3 routings = 2 updates + final) ----
        float bvec[32];
        #pragma unroll
        for (int q = 0; q < 32; q++) bvec[q] = 0.f;
        float v_[8];

        for (int iter = 0; iter < 3; iter++) {
            // p[t][z=lane] = sum_o uh[z][o][t] * sigmoid(b[o][t])
            float pt[8];
            #pragma unroll
            for (int t = 0; t < 8; t++) {
                float s = 0.f;
                #pragma unroll
                for (int o = 0; o < 4; o++) {
                    float r = 1.f / (1.f + expf(-bvec[o*8 + t]));
                    s = fmaf(uh[o*8 + t], r, s);
                }
                pt[t] = s;
            }
            // segmented (16-lane) reductions: max|p| for pos half, sum p^2 for app half
            #pragma unroll
            for (int t = 0; t < 8; t++) {
                float mv = fabsf(pt[t]);
                float sv = pt[t] * pt[t];
                #pragma unroll
                for (int d = 1; d < 16; d <<= 1) {
                    mv = fmaxf(mv, __shfl_xor_sync(0xffffffffu, mv, d));
                    sv +=            __shfl_xor_sync(0xffffffffu, sv, d);
                }
                if (app) {
                    float n2 = sv;
                    v_[t] = n2 / (1.f + n2) * pt[t] * rsqrtf(n2 + 1e-9f);
                } else {
                    v_[t] = pt[t] / mv;
                }
            }
            if (iter == 2) break;
            // rout[o][t] = (sum_{z<16} uh*v) * (sum_{z>=16} uh*v)
            #pragma unroll
            for (int o = 0; o < 4; o++) {
                #pragma unroll
                for (int t = 0; t < 8; t++) {
                    float s = uh[o*8 + t] * v_[t];
                    #pragma unroll
                    for (int d = 1; d < 16; d <<= 1)
                        s += __shfl_xor_sync(0xffffffffu, s, d);
                    float other = __shfl_xor_sync(0xffffffffu, s, 16);
                    bvec[o*8 + t] += s * other;
                }
            }
        }

        // ---- stage output: out[n, t, z=lane, hh, gw] = v_[t] ----
        #pragma unroll
        for (int t = 0; t < 8; t++)
            out_sh[(t*32 + lane)*33 + p] = v_[t];
    }

    __syncthreads();
    // ---- coalesced writeout: row = t*32+z, 128B stores ----
    #pragma unroll
    for (int it = 0; it < 32; it++) {
        int row = it * 8 + warp;
        out[(n*256 + row)*(HD*WD) + hh*WD + w0 + lane] = out_sh[row*33 + lane];
    }
}

extern "C" void kernel_launch(void* const* d_in, const int* in_sizes, int n_in,
                              void* d_out, int out_size)
{
    const float* inp = (const float*)d_in[0];   // (4,4,32,96,96)
    const float* Wc  = (const float*)d_in[1];   // (4,5,5,1,8)
    const float* Wp  = (const float*)d_in[2];   // (4,16,8)
    const float* Wa  = (const float*)d_in[3];   // (4,16,8)
    const float* ba  = (const float*)d_in[4];   // (4,8)
    float* out = (float*)d_out;                 // (4,8,32,96,96)

    const int smem_bytes = SMEM_F * (int)sizeof(float);
    cudaFuncSetAttribute(caps2d_fused_kernel,
                         cudaFuncAttributeMaxDynamicSharedMemorySize, smem_bytes);

    dim3 grid(WD / PXB, HD, NB);   // (3, 96, 4)
    dim3 block(256);
    caps2d_fused_kernel<<<grid, block, smem_bytes>>>(inp, Wc, Wp, Wa, ba, out);
}

// round 2
// speedup vs baseline: 1.7573x; 1.7573x over previous
#include <cuda_runtime.h>
#include <math.h>

// Problem constants
#define HD   96
#define WD   96
#define NB   4
// tile
#define PXB  16     // pixels (w) per block
#define NWARPS 8
#define PXW  2      // pixels per warp
#define XCOLS 20    // PXB + 4 halo

// shared layout (floats)
#define IN_CH_STRIDE 101             // 5*20 + 1 pad
#define IN_SH_F   (128*IN_CH_STRIDE) // 12928
#define CONV_SH_F (NWARPS*32*33)     // 8448 : per-warp conv[zz][o*8+j], zz-stride 33
#define OUT_SH_F  (256*17)           // 4352 : out[(t*32+z)][px], row-stride 17
#define WC_SH_F   800
#define MP_SH_F   512
#define MA_SH_F   512
#define BA_SH_F   32
#define SMEM_F (IN_SH_F + CONV_SH_F + OUT_SH_F + WC_SH_F + MP_SH_F + MA_SH_F + BA_SH_F)

__global__ void __launch_bounds__(256, 2)
caps2d_fused_kernel(const float* __restrict__ inp,
                    const float* __restrict__ Wc,
                    const float* __restrict__ Wp,
                    const float* __restrict__ Wa,
                    const float* __restrict__ ba,
                    float* __restrict__ out)
{
    extern __shared__ float smem[];
    float* in_sh   = smem;
    float* conv_sh = in_sh + IN_SH_F;
    float* out_sh  = conv_sh + CONV_SH_F;
    float* wc_sh   = out_sh + OUT_SH_F;
    float* mp_sh   = wc_sh + WC_SH_F;
    float* ma_sh   = mp_sh + MP_SH_F;
    float* ba_sh   = ma_sh + MA_SH_F;

    const int tid  = threadIdx.x;
    const int warp = tid >> 5;
    const int lane = tid & 31;
    const int w0   = blockIdx.x * PXB;
    const int hh   = blockIdx.y;
    const int n    = blockIdx.z;

    // ---- load small weights ----
    for (int e = tid; e < WC_SH_F; e += 256) wc_sh[e] = Wc[e];
    for (int e = tid; e < 512; e += 256) {
        int o = e >> 7, r = e & 127, t = r >> 4, b = r & 3;
        // column norm of W_pos[o] over k (axis=-2) for fixed (t,b)
        float s = 0.f;
        #pragma unroll
        for (int kk = 0; kk < 4; kk++) {
            float v = Wp[o*128 + t*16 + kk*4 + b];
            s += v * v;
        }
        float nrm = sqrtf(fmaxf(s, 1e-12f));
        mp_sh[e] = Wp[e] / nrm;   // e == o*128 + t*16 + k*4 + b
        ma_sh[e] = Wa[e];
    }
    if (tid < 32) ba_sh[tid] = ba[tid];

    // ---- load input halo tile: ch in [0,128), y in [0,5), x in [0,20) ----
    for (int e = tid; e < 128*100; e += 256) {
        int ch = e / 100;
        int r  = e - ch * 100;
        int y  = r / XCOLS;
        int x  = r - y * XCOLS;
        int gy = hh + y - 2;
        int gx = w0 + x - 2;
        float v = 0.f;
        if (gy >= 0 && gy < HD && gx >= 0 && gx < WD)
            v = inp[((n*128 + ch)*HD + gy)*WD + gx];
        in_sh[ch*IN_CH_STRIDE + y*XCOLS + x] = v;
    }
    __syncthreads();

    const int a_  = (lane >> 2) & 3;   // pose/app matrix row
    const int bb  = lane & 3;          // pose/app matrix col
    const int app = lane >> 4;         // 0 = pos half (z<16), 1 = app half
    float* csh = conv_sh + warp * (32*33);

    const float cy = (float)hh * (1.f/96.f);

    for (int ip = 0; ip < PXW; ip++) {
        const int p  = warp * PXW + ip;
        const int gw = w0 + p;

        // ---- phase 1: depthwise 5x5 conv for zz = lane, all o, 8 filters ----
        __syncwarp();
        {
            float acc[32];
            #pragma unroll
            for (int q = 0; q < 32; q++) acc[q] = 0.f;
            #pragma unroll
            for (int o = 0; o < 4; o++) {
                const float* ib = in_sh + (o*32 + lane)*IN_CH_STRIDE;
                #pragma unroll
                for (int ky = 0; ky < 5; ky++) {
                    #pragma unroll
                    for (int kx = 0; kx < 5; kx++) {
                        float v = ib[ky*XCOLS + p + kx];
                        const float* wr = wc_sh + ((o*5 + ky)*5 + kx)*8;
                        #pragma unroll
                        for (int j = 0; j < 8; j++)
                            acc[o*8 + j] = fmaf(v, wr[j], acc[o*8 + j]);
                    }
                }
            }
            #pragma unroll
            for (int q = 0; q < 32; q++) csh[lane*33 + q] = acc[q];
        }
        __syncwarp();

        // ---- phase 2: u_hat[z=lane][o][t] ----
        float uh[32];
        const float cx = (float)gw * (1.f/96.f);
        #pragma unroll
        for (int o = 0; o < 4; o++) {
            #pragma unroll
            for (int t = 0; t < 8; t++) {
                const int j    = (app ? 4 : 0) + (t >> 1);
                const int zb   = ((t & 1) << 4) + (a_ << 2);
                const float bias = app ? ba_sh[o*8 + t] : 0.f;
                float s = 0.f;
                #pragma unroll
                for (int k = 0; k < 4; k++) {
                    float c = csh[(zb + k)*33 + o*8 + j] + bias;
                    float m;
                    if (app) {
                        m = ma_sh[o*128 + t*16 + k*4 + bb];
                    } else {
                        m = mp_sh[o*128 + t*16 + k*4 + bb];
                        if (k == 3) {
                            if (bb == 0)      m += cx;
                            else if (bb == 1) m += cy;
                        }
                    }
                    s = fmaf(c, m, s);
                }
                uh[o*8 + t] = s;
            }
        }

        // ---- phase 3: dynamic routing (3 routings = 2 updates + final) ----
        float bvec[32];
        #pragma unroll
        for (int q = 0; q < 32; q++) bvec[q] = 0.f;
        float v_[8];

        for (int iter = 0; iter < 3; iter++) {
            // p[t][z=lane] = sum_o uh[z][o][t] * sigmoid(b[o][t])
            float pt[8];
            if (iter == 0) {
                // b == 0 -> sigmoid == 0.5 for all terms
                #pragma unroll
                for (int t = 0; t < 8; t++) {
                    float s = uh[t] + uh[8 + t] + uh[16 + t] + uh[24 + t];
                    pt[t] = 0.5f * s;
                }
            } else {
                #pragma unroll
                for (int t = 0; t < 8; t++) {
                    float s = 0.f;
                    #pragma unroll
                    for (int o = 0; o < 4; o++) {
                        float r = 1.f / (1.f + __expf(-bvec[o*8 + t]));
                        s = fmaf(uh[o*8 + t], r, s);
                    }
                    pt[t] = s;
                }
            }
            // segmented (16-lane) reductions: max|p| for pos half, sum p^2 for app half
            #pragma unroll
            for (int t = 0; t < 8; t++) {
                float mv = fabsf(pt[t]);
                float sv = pt[t] * pt[t];
                #pragma unroll
                for (int d = 1; d < 16; d <<= 1) {
                    mv = fmaxf(mv, __shfl_xor_sync(0xffffffffu, mv, d));
                    sv +=            __shfl_xor_sync(0xffffffffu, sv, d);
                }
                if (app) {
                    float n2 = sv;
                    v_[t] = n2 / (1.f + n2) * pt[t] * rsqrtf(n2 + 1e-9f);
                } else {
                    v_[t] = pt[t] / mv;
                }
            }
            if (iter == 2) break;
            // rout[o][t] = (sum_{z<16} uh*v) * (sum_{z>=16} uh*v)
            #pragma unroll
            for (int o = 0; o < 4; o++) {
                #pragma unroll
                for (int t = 0; t < 8; t++) {
                    float s = uh[o*8 + t] * v_[t];
                    #pragma unroll
                    for (int d = 1; d < 16; d <<= 1)
                        s += __shfl_xor_sync(0xffffffffu, s, d);
                    float other = __shfl_xor_sync(0xffffffffu, s, 16);
                    bvec[o*8 + t] += s * other;
                }
            }
        }

        // ---- stage output: out[n, t, z=lane, hh, gw] = v_[t] ----
        #pragma unroll
        for (int t = 0; t < 8; t++)
            out_sh[(t*32 + lane)*17 + p] = v_[t];
    }

    __syncthreads();
    // ---- coalesced writeout: 256 rows x 16 px ----
    for (int e = tid; e < 256*16; e += 256) {
        int row = e >> 4;
        int x   = e & 15;
        out[(n*256 + row)*(HD*WD) + hh*WD + w0 + x] = out_sh[row*17 + x];
    }
}

extern "C" void kernel_launch(void* const* d_in, const int* in_sizes, int n_in,
                              void* d_out, int out_size)
{
    const float* inp = (const float*)d_in[0];   // (4,4,32,96,96)
    const float* Wc  = (const float*)d_in[1];   // (4,5,5,1,8)
    const float* Wp  = (const float*)d_in[2];   // (4,16,8)
    const float* Wa  = (const float*)d_in[3];   // (4,16,8)
    const float* ba  = (const float*)d_in[4];   // (4,8)
    float* out = (float*)d_out;                 // (4,8,32,96,96)

    const int smem_bytes = SMEM_F * (int)sizeof(float);
    cudaFuncSetAttribute(caps2d_fused_kernel,
                         cudaFuncAttributeMaxDynamicSharedMemorySize, smem_bytes);

    dim3 grid(WD / PXB, HD, NB);   // (6, 96, 4)
    dim3 block(256);
    caps2d_fused_kernel<<<grid, block, smem_bytes>>>(inp, Wc, Wp, Wa, ba, out);
}

// round 3
// speedup vs baseline: 1.9015x; 1.0820x over previous
#include <cuda_runtime.h>
#include <math.h>

// Problem constants
#define HD   96
#define WD   96
// tile
#define PXB  8      // pixels (w) per block
#define NWARPS 16   // warp pair per pixel: half 0 -> t 0..3, half 1 -> t 4..7
#define XCOLS 12    // PXB + 4 halo

// shared layout (floats)
#define IN_CH_STRIDE 61              // 5*12 + 1 pad (odd -> conflict-free ch stride)
#define IN_SH_F   (128*IN_CH_STRIDE) // 7808
#define CONV_SH_F (NWARPS*16*33)     // 8448 : per-warp conv[col q][z], col-stride 33
#define WC_SH_F   800                // rearranged: [half][tap][4]
#define MP_SH_F   512
#define MA_SH_F   512
#define BA_SH_F   32
#define SMEM_F (IN_SH_F + CONV_SH_F + WC_SH_F + MP_SH_F + MA_SH_F + BA_SH_F)

__global__ void __launch_bounds__(512, 2)
caps2d_fused_kernel(const float* __restrict__ inp,
                    const float* __restrict__ Wc,
                    const float* __restrict__ Wp,
                    const float* __restrict__ Wa,
                    const float* __restrict__ ba,
                    float* __restrict__ out)
{
    extern __shared__ float smem[];
    float* in_sh   = smem;
    float* conv_sh = in_sh + IN_SH_F;
    float* wc_sh   = conv_sh + CONV_SH_F;
    float* mp_sh   = wc_sh + WC_SH_F;
    float* ma_sh   = mp_sh + MP_SH_F;
    float* ba_sh   = ma_sh + MA_SH_F;

    const int tid  = threadIdx.x;
    const int warp = tid >> 5;
    const int lane = tid & 31;
    const int w0   = blockIdx.x * PXB;
    const int hh   = blockIdx.y;
    const int n    = blockIdx.z;

    // ---- load + rearrange conv weights: wc_sh[h][tap][jj], jj->j map per half ----
    for (int e = tid; e < 800; e += 512) {
        int h   = e / 400;
        int r   = e - h * 400;
        int tap = r >> 2;
        int jj  = r & 3;
        int j   = h * 2 + (jj & 1) + ((jj >> 1) << 2);  // {0,1,4,5} or {2,3,6,7}
        wc_sh[e] = Wc[tap * 8 + j];
    }
    if (tid < 512) {
        int e = tid;
        int o = e >> 7, r = e & 127, t = r >> 4, b = r & 3;
        // column norm of W_pos[o] over k (axis=-2) for fixed (t,b)
        float s = 0.f;
        #pragma unroll
        for (int kk = 0; kk < 4; kk++) {
            float v = Wp[o*128 + t*16 + kk*4 + b];
            s += v * v;
        }
        float nrm = sqrtf(fmaxf(s, 1e-12f));
        mp_sh[e] = Wp[e] / nrm;   // e == o*128 + t*16 + k*4 + b
        ma_sh[e] = Wa[e];
    }
    if (tid < 32) ba_sh[tid] = ba[tid];

    // ---- load input halo tile: ch in [0,128), y in [0,5), x in [0,12) ----
    for (int e = tid; e < 128*60; e += 512) {
        int ch = e / 60;
        int r  = e - ch * 60;
        int y  = r / XCOLS;
        int x  = r - y * XCOLS;
        int gy = hh + y - 2;
        int gx = w0 + x - 2;
        float v = 0.f;
        if (gy >= 0 && gy < HD && gx >= 0 && gx < WD)
            v = inp[((n*128 + ch)*HD + gy)*WD + gx];
        in_sh[ch*IN_CH_STRIDE + y*XCOLS + x] = v;
    }
    __syncthreads();

    const int half = warp & 1;         // t half: 0 -> t 0..3, 1 -> t 4..7
    const int p    = warp >> 1;        // pixel within tile
    const int gw   = w0 + p;
    const int a_   = (lane >> 2) & 3;  // pose/app matrix row
    const int bb   = lane & 3;         // pose/app matrix col
    const int app  = lane >> 4;        // 0 = pos half (z<16), 1 = app half
    float* csh = conv_sh + warp * (16*33);

    const float cy = (float)hh * (1.f/96.f);
    const float cx = (float)gw * (1.f/96.f);

    // ---- phase 1: depthwise 5x5 conv for z = o*32+lane, this half's 4 filters ----
    {
        float acc[16];
        #pragma unroll
        for (int q = 0; q < 16; q++) acc[q] = 0.f;
        const float* wcb = wc_sh + half * 400;
        #pragma unroll
        for (int o = 0; o < 4; o++) {
            const float* ib = in_sh + (o*32 + lane)*IN_CH_STRIDE;
            #pragma unroll
            for (int ky = 0; ky < 5; ky++) {
                #pragma unroll
                for (int kx = 0; kx < 5; kx++) {
                    float v = ib[ky*XCOLS + p + kx];
                    const float* wr = wcb + ((o*5 + ky)*5 + kx)*4;
                    #pragma unroll
                    for (int jj = 0; jj < 4; jj++)
                        acc[o*4 + jj] = fmaf(v, wr[jj], acc[o*4 + jj]);
                }
            }
        }
        __syncwarp();
        #pragma unroll
        for (int q = 0; q < 16; q++) csh[q*33 + lane] = acc[q];
    }
    __syncwarp();

    // ---- phase 2: u_hat[z=lane][o][tt] for this half's 4 t values ----
    float uh[16];
    #pragma unroll
    for (int o = 0; o < 4; o++) {
        #pragma unroll
        for (int tt = 0; tt < 4; tt++) {
            const int t   = half*4 + tt;
            const int jjc = (app ? 2 : 0) + (tt >> 1);     // column in this half's conv set
            const int zb  = ((tt & 1) << 4) + (a_ << 2);
            const float bias = app ? ba_sh[o*8 + t] : 0.f;
            const float* crow = csh + (o*4 + jjc)*33;
            float s = 0.f;
            #pragma unroll
            for (int k = 0; k < 4; k++) {
                float c = crow[zb + k] + bias;
                float m;
                if (app) {
                    m = ma_sh[o*128 + t*16 + k*4 + bb];
                } else {
                    m = mp_sh[o*128 + t*16 + k*4 + bb];
                    if (k == 3) {
                        if (bb == 0)      m += cx;
                        else if (bb == 1) m += cy;
                    }
                }
                s = fmaf(c, m, s);
            }
            uh[o*4 + tt] = s;
        }
    }

    // ---- phase 3: dynamic routing (3 routings = 2 updates + final) ----
    float bvec[16];
    #pragma unroll
    for (int q = 0; q < 16; q++) bvec[q] = 0.f;
    float v_[4];

    for (int iter = 0; iter < 3; iter++) {
        // p[tt][z=lane] = sum_o uh[z][o][tt] * sigmoid(b[o][tt])
        float pt[4];
        if (iter == 0) {
            // b == 0 -> sigmoid == 0.5 for all terms
            #pragma unroll
            for (int tt = 0; tt < 4; tt++)
                pt[tt] = 0.5f * (uh[tt] + uh[4 + tt] + uh[8 + tt] + uh[12 + tt]);
        } else {
            #pragma unroll
            for (int tt = 0; tt < 4; tt++) {
                float s = 0.f;
                #pragma unroll
                for (int o = 0; o < 4; o++) {
                    float r = 1.f / (1.f + __expf(-bvec[o*4 + tt]));
                    s = fmaf(uh[o*4 + tt], r, s);
                }
                pt[tt] = s;
            }
        }
        // segmented (16-lane) reductions: max|p| for pos half, sum p^2 for app half
        #pragma unroll
        for (int tt = 0; tt < 4; tt++) {
            float mv = fabsf(pt[tt]);
            float sv = pt[tt] * pt[tt];
            #pragma unroll
            for (int d = 1; d < 16; d <<= 1) {
                mv = fmaxf(mv, __shfl_xor_sync(0xffffffffu, mv, d));
                sv +=            __shfl_xor_sync(0xffffffffu, sv, d);
            }
            if (app) {
                float n2 = sv;
                v_[tt] = n2 / (1.f + n2) * pt[tt] * rsqrtf(n2 + 1e-9f);
            } else {
                v_[tt] = pt[tt] / mv;
            }
        }
        if (iter == 2) break;
        // rout[o][tt] = (sum_{z<16} uh*v) * (sum_{z>=16} uh*v)
        #pragma unroll
        for (int o = 0; o < 4; o++) {
            #pragma unroll
            for (int tt = 0; tt < 4; tt++) {
                float s = uh[o*4 + tt] * v_[tt];
                #pragma unroll
                for (int d = 1; d < 16; d <<= 1)
                    s += __shfl_xor_sync(0xffffffffu, s, d);
                float other = __shfl_xor_sync(0xffffffffu, s, 16);
                bvec[o*4 + tt] += s * other;
            }
        }
    }

    // ---- direct writeout: out[n, t*32+z, hh, gw] ; L2 merges the 8-px rows ----
    #pragma unroll
    for (int tt = 0; tt < 4; tt++) {
        int row = (half*4 + tt)*32 + lane;
        out[(n*256 + row)*(HD*WD) + hh*WD + gw] = v_[tt];
    }
}

extern "C" void kernel_launch(void* const* d_in, const int* in_sizes, int n_in,
                              void* d_out, int out_size)
{
    const float* inp = (const float*)d_in[0];   // (4,4,32,96,96)
    const float* Wc  = (const float*)d_in[1];   // (4,5,5,1,8)
    const float* Wp  = (const float*)d_in[2];   // (4,16,8)
    const float* Wa  = (const float*)d_in[3];   // (4,16,8)
    const float* ba  = (const float*)d_in[4];   // (4,8)
    float* out = (float*)d_out;                 // (4,8,32,96,96)

    const int smem_bytes = SMEM_F * (int)sizeof(float);
    cudaFuncSetAttribute(caps2d_fused_kernel,
                         cudaFuncAttributeMaxDynamicSharedMemorySize, smem_bytes);

    dim3 grid(WD / PXB, HD, 4);   // (12, 96, 4)
    dim3 block(512);
    caps2d_fused_kernel<<<grid, block, smem_bytes>>>(inp, Wc, Wp, Wa, ba, out);
}

// round 4
// speedup vs baseline: 2.2135x; 1.1641x over previous
#include <cuda_runtime.h>
#include <math.h>

// Problem constants
#define HD   96
#define WD   96
// tile
#define PXB  8      // pixels (w) per block
#define XCOLS 12    // PXB + 4 halo

// shared layout (floats)
#define IN_CH_STRIDE 61              // 5*12 + 1 pad (odd -> conflict-free ch stride)
#define IN_SH_F   (128*IN_CH_STRIDE) // 7808 (multiple of 4 -> 16B alignment holds after)
#define CONV_SH_F (PXB*32*36)        // 9216 : conv[p][o*8+j][z], col-stride 36 (16B aligned)
#define WC_SH_F   800                // [tap][j]
#define MP_SH_F   512                // [o][t][bb][k]  (k contiguous -> LDS.128)
#define MA_SH_F   512
#define BA_SH_F   32
#define SMEM_F (IN_SH_F + CONV_SH_F + WC_SH_F + MP_SH_F + MA_SH_F + BA_SH_F)

__global__ void __launch_bounds__(512, 2)
caps2d_fused_kernel(const float* __restrict__ inp,
                    const float* __restrict__ Wc,
                    const float* __restrict__ Wp,
                    const float* __restrict__ Wa,
                    const float* __restrict__ ba,
                    float* __restrict__ out)
{
    extern __shared__ float smem[];
    float* in_sh   = smem;
    float* conv_sh = in_sh + IN_SH_F;
    float* wc_sh   = conv_sh + CONV_SH_F;
    float* mp_sh   = wc_sh + WC_SH_F;
    float* ma_sh   = mp_sh + MP_SH_F;
    float* ba_sh   = ma_sh + MA_SH_F;

    const int tid  = threadIdx.x;
    const int warp = tid >> 5;
    const int lane = tid & 31;
    const int w0   = blockIdx.x * PXB;
    const int hh   = blockIdx.y;
    const int n    = blockIdx.z;

    // ---- load conv weights [tap][j] (natural layout) ----
    for (int e = tid; e < 800; e += 512) wc_sh[e] = Wc[e];

    // ---- load + relayout pose/app matrices: dst [o][t][bb][k] ----
    if (tid < 512) {
        int q8 = tid >> 4;           // o*8 + t
        int bb = (tid >> 2) & 3;
        int k  = tid & 3;
        int o  = q8 >> 3, t = q8 & 7;
        int src = o*128 + t*16 + k*4 + bb;
        // column norm of W_pos[o] over k (axis=-2) for fixed (t,bb)
        float s = 0.f;
        #pragma unroll
        for (int kk = 0; kk < 4; kk++) {
            float v = Wp[o*128 + t*16 + kk*4 + bb];
            s += v * v;
        }
        float nrm = sqrtf(fmaxf(s, 1e-12f));
        mp_sh[tid] = Wp[src] / nrm;
        ma_sh[tid] = Wa[src];
    }
    if (tid < 32) ba_sh[tid] = ba[tid];

    // ---- load input halo tile: ch in [0,128), y in [0,5), x in [0,12) ----
    for (int e = tid; e < 128*60; e += 512) {
        int ch = e / 60;
        int r  = e - ch * 60;
        int y  = r / XCOLS;
        int x  = r - y * XCOLS;
        int gy = hh + y - 2;
        int gx = w0 + x - 2;
        float v = 0.f;
        if (gy >= 0 && gy < HD && gx >= 0 && gx < WD)
            v = inp[((n*128 + ch)*HD + gy)*WD + gx];
        in_sh[ch*IN_CH_STRIDE + y*XCOLS + x] = v;
    }
    __syncthreads();

    const int half = warp & 1;         // conv: o-pair {2h,2h+1}; routing: t-half
    const int p    = warp >> 1;        // pixel within tile
    const int gw   = w0 + p;
    const int a_   = (lane >> 2) & 3;  // pose/app matrix row
    const int bb   = lane & 3;         // pose/app matrix col
    const bool app = (lane >> 4) != 0; // 0 = pos half (z<16), 1 = app half
    float* csh = conv_sh + p * (32*36);

    const float cy = (float)hh * (1.f/96.f);
    const float cx = (float)gw * (1.f/96.f);

    // ---- phase 1: depthwise 5x5 conv. warp handles o in {2*half, 2*half+1}, all 8 j ----
    {
        float acc[16];
        #pragma unroll
        for (int q = 0; q < 16; q++) acc[q] = 0.f;
        #pragma unroll
        for (int oo = 0; oo < 2; oo++) {
            const int o = half*2 + oo;
            const float* ib = in_sh + (o*32 + lane)*IN_CH_STRIDE;
            #pragma unroll
            for (int ky = 0; ky < 5; ky++) {
                #pragma unroll
                for (int kx = 0; kx < 5; kx++) {
                    float v = ib[ky*XCOLS + p + kx];
                    const float* wr = wc_sh + ((o*5 + ky)*5 + kx)*8;
                    #pragma unroll
                    for (int j = 0; j < 8; j++)
                        acc[oo*8 + j] = fmaf(v, wr[j], acc[oo*8 + j]);
                }
            }
        }
        #pragma unroll
        for (int oo = 0; oo < 2; oo++)
            #pragma unroll
            for (int j = 0; j < 8; j++)
                csh[((half*2 + oo)*8 + j)*36 + lane] = acc[oo*8 + j];
    }
    __syncthreads();   // join warp pair: phase 2 reads all o

    // ---- phase 2: u_hat[z=lane][q = o*4+tt], this half's 4 t values ----
    float uh[16];
    #pragma unroll
    for (int o = 0; o < 4; o++) {
        #pragma unroll
        for (int tt = 0; tt < 4; tt++) {
            const int t  = half*4 + tt;
            const int j  = (app ? 4 : 0) + (t >> 1);     // conv filter column
            const int zb = ((t & 1) << 4) + (a_ << 2);
            const float bias = app ? ba_sh[o*8 + t] : 0.f;
            const float4 cv = *reinterpret_cast<const float4*>(csh + (o*8 + j)*36 + zb);
            const float* msrc = (app ? ma_sh : mp_sh) + ((o*8 + t)*4 + bb)*4;
            float4 m = *reinterpret_cast<const float4*>(msrc);
            if (!app) {
                if (bb == 0)      m.w += cx;
                else if (bb == 1) m.w += cy;
            }
            float s;
            s = (cv.x + bias) * m.x;
            s = fmaf(cv.y + bias, m.y, s);
            s = fmaf(cv.z + bias, m.z, s);
            s = fmaf(cv.w + bias, m.w, s);
            uh[o*4 + tt] = s;
        }
    }

    // ---- phase 3: dynamic routing, b distributed (lane q = lane&15 owns b_q) ----
    const unsigned FULL = 0xffffffffu;
    const bool b0 = (lane & 1) != 0;
    const bool b1 = (lane & 2) != 0;
    const bool b2 = (lane & 4) != 0;
    const bool b3 = (lane & 8) != 0;
    float bq = 0.f;
    float v_[4];

    for (int iter = 0; iter < 3; iter++) {
        // p[tt] = sum_o uh[o*4+tt] * sigmoid(b[o*4+tt])
        float pt[4];
        if (iter == 0) {
            #pragma unroll
            for (int tt = 0; tt < 4; tt++)
                pt[tt] = 0.5f * (uh[tt] + uh[4 + tt] + uh[8 + tt] + uh[12 + tt]);
        } else {
            float rq = 1.f / (1.f + __expf(-bq));   // sigmoid of my owned b
            #pragma unroll
            for (int tt = 0; tt < 4; tt++) {
                float s = 0.f;
                #pragma unroll
                for (int o = 0; o < 4; o++) {
                    float r = __shfl_sync(FULL, rq, (lane & 16) | (o*4 + tt));
                    s = fmaf(uh[o*4 + tt], r, s);
                }
                pt[tt] = s;
            }
        }
        // segmented 16-lane norms: pos lanes need max|p|, app lanes need sum p^2
        #pragma unroll
        for (int tt = 0; tt < 4; tt++) {
            float x = app ? pt[tt]*pt[tt] : fabsf(pt[tt]);
            #pragma unroll
            for (int d = 1; d < 16; d <<= 1) {
                float y = __shfl_xor_sync(FULL, x, d);
                x = app ? (x + y) : fmaxf(x, y);
            }
            if (app) {
                v_[tt] = x / (1.f + x) * pt[tt] * rsqrtf(x + 1e-9f);
            } else {
                v_[tt] = pt[tt] / x;
            }
        }
        if (iter == 2) break;

        // multi-value butterfly: R_q = sum over own 16-half of uh[q]*v_[q&3],
        // result for q = lane&15 lands on this lane. 15 shfl total.
        float t8[8];
        #pragma unroll
        for (int j = 0; j < 8; j++) {
            float sa = uh[2*j]     * v_[(2*j)     & 3];
            float sb = uh[2*j + 1] * v_[(2*j + 1) & 3];
            float keep = b0 ? sb : sa;
            float send = b0 ? sa : sb;
            t8[j] = keep + __shfl_xor_sync(FULL, send, 1);
        }
        float t4[4];
        #pragma unroll
        for (int j = 0; j < 4; j++) {
            float keep = b1 ? t8[2*j + 1] : t8[2*j];
            float send = b1 ? t8[2*j]     : t8[2*j + 1];
            t4[j] = keep + __shfl_xor_sync(FULL, send, 2);
        }
        float t2[2];
        #pragma unroll
        for (int j = 0; j < 2; j++) {
            float keep = b2 ? t4[2*j + 1] : t4[2*j];
            float send = b2 ? t4[2*j]     : t4[2*j + 1];
            t2[j] = keep + __shfl_xor_sync(FULL, send, 4);
        }
        {
            float keep = b3 ? t2[1] : t2[0];
            float send = b3 ? t2[0] : t2[1];
            float R = keep + __shfl_xor_sync(FULL, send, 8);
            float other = __shfl_xor_sync(FULL, R, 16);   // cross pos/app halves
            bq = fmaf(R, other, bq);
        }
    }

    // ---- direct writeout: out[n, (half*4+tt)*32 + z, hh, gw] ----
    #pragma unroll
    for (int tt = 0; tt < 4; tt++) {
        int row = (half*4 + tt)*32 + lane;
        out[(n*256 + row)*(HD*WD) + hh*WD + gw] = v_[tt];
    }
}

extern "C" void kernel_launch(void* const* d_in, const int* in_sizes, int n_in,
                              void* d_out, int out_size)
{
    const float* inp = (const float*)d_in[0];   // (4,4,32,96,96)
    const float* Wc  = (const float*)d_in[1];   // (4,5,5,1,8)
    const float* Wp  = (const float*)d_in[2];   // (4,16,8)
    const float* Wa  = (const float*)d_in[3];   // (4,16,8)
    const float* ba  = (const float*)d_in[4];   // (4,8)
    float* out = (float*)d_out;                 // (4,8,32,96,96)

    const int smem_bytes = SMEM_F * (int)sizeof(float);
    cudaFuncSetAttribute(caps2d_fused_kernel,
                         cudaFuncAttributeMaxDynamicSharedMemorySize, smem_bytes);

    dim3 grid(WD / PXB, HD, 4);   // (12, 96, 4)
    dim3 block(512);
    caps2d_fused_kernel<<<grid, block, smem_bytes>>>(inp, Wc, Wp, Wa, ba, out);
}

// round 5
// speedup vs baseline: 2.6022x; 1.1756x over previous
#include <cuda_runtime.h>
#include <math.h>

// Problem constants
#define HD   96
#define WD   96
// tile
#define PXB  8      // pixels (w) per block
#define XCOLS 12    // PXB + 4 halo

// shared layout (floats)
#define IN_CH_STRIDE 61              // 5*12 + 1 pad (odd -> conflict-free lane stride)
#define IN_SH_F   (128*IN_CH_STRIDE) // 7808
#define CONV_SH_F (PXB*32*36)        // 9216 : conv[p][o*8+j][z], col-stride 36 (16B aligned)
#define WC_SH_F   800                // [o][ky][kx][j]
#define MP_SH_F   512                // [o][t][bb][k]  (k contiguous -> LDS.128)
#define MA_SH_F   512
#define MB_SH_F   128                // b_app * sum_k m_app  per (o,t,bb)
#define SMEM_F (IN_SH_F + CONV_SH_F + WC_SH_F + MP_SH_F + MA_SH_F + MB_SH_F)

__global__ void __launch_bounds__(512, 2)
caps2d_fused_kernel(const float* __restrict__ inp,
                    const float* __restrict__ Wc,
                    const float* __restrict__ Wp,
                    const float* __restrict__ Wa,
                    const float* __restrict__ ba,
                    float* __restrict__ out)
{
    extern __shared__ float smem[];
    float* in_sh   = smem;
    float* conv_sh = in_sh + IN_SH_F;
    float* wc_sh   = conv_sh + CONV_SH_F;
    float* mp_sh   = wc_sh + WC_SH_F;
    float* ma_sh   = mp_sh + MP_SH_F;
    float* mb_sh   = ma_sh + MA_SH_F;

    const int tid  = threadIdx.x;
    const int warp = tid >> 5;
    const int lane = tid & 31;
    const int w0   = blockIdx.x * PXB;
    const int hh   = blockIdx.y;
    const int n    = blockIdx.z;

    // ---- load conv weights [o][tap][j] (natural layout) ----
    for (int e = tid; e < 800; e += 512) wc_sh[e] = Wc[e];

    // ---- load + relayout pose/app matrices: dst [o][t][bb][k] ----
    {
        int q8 = tid >> 4;           // o*8 + t
        int bb = (tid >> 2) & 3;
        int k  = tid & 3;
        int o  = q8 >> 3, t = q8 & 7;
        int src = o*128 + t*16 + k*4 + bb;
        // column norm of W_pos[o] over k (axis=-2) for fixed (t,bb)
        float s = 0.f;
        #pragma unroll
        for (int kk = 0; kk < 4; kk++) {
            float v = Wp[o*128 + t*16 + kk*4 + bb];
            s += v * v;
        }
        float nrm = sqrtf(fmaxf(s, 1e-12f));
        mp_sh[tid] = Wp[src] / nrm;
        ma_sh[tid] = Wa[src];
    }
    // ---- precompute folded app bias: mb[(o*8+t)*4+bb] = ba[o,t] * sum_k Wa[o,t,k,bb] ----
    if (tid < 128) {
        int bb = tid & 3, t = (tid >> 2) & 7, o = tid >> 5;
        float sm = 0.f;
        #pragma unroll
        for (int k = 0; k < 4; k++) sm += Wa[o*128 + t*16 + k*4 + bb];
        mb_sh[tid] = ba[o*8 + t] * sm;
    }

    // ---- load input halo tile, division-free: thread owns fixed (y,x), walks ch ----
    {
        int id  = tid & 63;          // 64 threads cover 60 (y,x) slots
        int y   = id / 12;
        int x   = id - y * 12;
        int ch0 = tid >> 6;          // 0..7 ; ch = ch0 + 8*c
        int gy  = hh + y - 2;
        int gx  = w0 + x - 2;
        bool ok = (id < 60) && (gy >= 0) && (gy < HD) && (gx >= 0) && (gx < WD);
        const float* src = inp + ((n*128 + ch0)*HD + gy)*WD + gx;
        float* dst = in_sh + ch0*IN_CH_STRIDE + y*XCOLS + x;
        #pragma unroll
        for (int c = 0; c < 16; c++) {
            if (id < 60) dst[0] = ok ? src[0] : 0.f;
            src += 8*HD*WD;
            dst += 8*IN_CH_STRIDE;
        }
    }
    __syncthreads();

    // ---- phase 1: depthwise 5x5 conv. warp = (o = warp&3, pixel pair pg = warp>>2) ----
    {
        const int o  = warp & 3;
        const int p0 = (warp >> 2) * 2;
        float acc[16];               // [px2][j=8]
        #pragma unroll
        for (int q = 0; q < 16; q++) acc[q] = 0.f;
        const float* ib  = in_sh + (o*32 + lane)*IN_CH_STRIDE;
        const float* wcb = wc_sh + o*200;
        #pragma unroll
        for (int ky = 0; ky < 5; ky++) {
            float r[6];
            #pragma unroll
            for (int q = 0; q < 6; q++) r[q] = ib[ky*XCOLS + p0 + q];
            #pragma unroll
            for (int kx = 0; kx < 5; kx++) {
                const float4 wa = *reinterpret_cast<const float4*>(wcb + (ky*5 + kx)*8);
                const float4 wb = *reinterpret_cast<const float4*>(wcb + (ky*5 + kx)*8 + 4);
                const float va = r[kx];
                const float vb = r[kx + 1];
                acc[0] = fmaf(va, wa.x, acc[0]);
                acc[1] = fmaf(va, wa.y, acc[1]);
                acc[2] = fmaf(va, wa.z, acc[2]);
                acc[3] = fmaf(va, wa.w, acc[3]);
                acc[4] = fmaf(va, wb.x, acc[4]);
                acc[5] = fmaf(va, wb.y, acc[5]);
                acc[6] = fmaf(va, wb.z, acc[6]);
                acc[7] = fmaf(va, wb.w, acc[7]);
                acc[8]  = fmaf(vb, wa.x, acc[8]);
                acc[9]  = fmaf(vb, wa.y, acc[9]);
                acc[10] = fmaf(vb, wa.z, acc[10]);
                acc[11] = fmaf(vb, wa.w, acc[11]);
                acc[12] = fmaf(vb, wb.x, acc[12]);
                acc[13] = fmaf(vb, wb.y, acc[13]);
                acc[14] = fmaf(vb, wb.z, acc[14]);
                acc[15] = fmaf(vb, wb.w, acc[15]);
            }
        }
        float* c0 = conv_sh + p0*(32*36)       + (o*8)*36 + lane;
        float* c1 = conv_sh + (p0 + 1)*(32*36) + (o*8)*36 + lane;
        #pragma unroll
        for (int j = 0; j < 8; j++) {
            c0[j*36] = acc[j];
            c1[j*36] = acc[8 + j];
        }
    }
    __syncthreads();   // role swap: conv (o,pg) -> routing (pixel, t-half)

    const int half = warp & 1;         // t half: 0 -> t 0..3, 1 -> t 4..7
    const int p    = warp >> 1;        // pixel within tile
    const int gw   = w0 + p;
    const int a_   = (lane >> 2) & 3;  // pose/app matrix row
    const int bb   = lane & 3;         // pose/app matrix col
    const bool app = (lane >> 4) != 0; // 0 = pos half (z<16), 1 = app half
    float* csh = conv_sh + p * (32*36);

    const float cy = (float)hh * (1.f/96.f);
    const float cx = (float)gw * (1.f/96.f);

    // ---- phase 2: u_hat[z=lane][q = o*4+tt], this half's 4 t values ----
    float uh[16];
    #pragma unroll
    for (int o = 0; o < 4; o++) {
        #pragma unroll
        for (int tt = 0; tt < 4; tt++) {
            const int t  = half*4 + tt;
            const int j  = (app ? 4 : 0) + (t >> 1);     // conv filter column
            const int zb = ((t & 1) << 4) + (a_ << 2);
            const float4 cv = *reinterpret_cast<const float4*>(csh + (o*8 + j)*36 + zb);
            const float* msrc = (app ? ma_sh : mp_sh) + ((o*8 + t)*4 + bb)*4;
            float4 m = *reinterpret_cast<const float4*>(msrc);
            float s0 = 0.f;
            if (app) {
                s0 = mb_sh[(o*8 + t)*4 + bb];
            } else {
                if (bb == 0)      m.w += cx;
                else if (bb == 1) m.w += cy;
            }
            float s;
            s = fmaf(cv.x, m.x, s0);
            s = fmaf(cv.y, m.y, s);
            s = fmaf(cv.z, m.z, s);
            s = fmaf(cv.w, m.w, s);
            uh[o*4 + tt] = s;
        }
    }

    // ---- phase 3: dynamic routing, b distributed (lane q = lane&15 owns b_q) ----
    const unsigned FULL = 0xffffffffu;
    const bool b0 = (lane & 1) != 0;
    const bool b1 = (lane & 2) != 0;
    const bool b2 = (lane & 4) != 0;
    const bool b3 = (lane & 8) != 0;
    float bq = 0.f;
    float v_[4];

    for (int iter = 0; iter < 3; iter++) {
        // p[tt] = sum_o uh[o*4+tt] * sigmoid(b[o*4+tt])
        float pt[4];
        if (iter == 0) {
            #pragma unroll
            for (int tt = 0; tt < 4; tt++)
                pt[tt] = 0.5f * (uh[tt] + uh[4 + tt] + uh[8 + tt] + uh[12 + tt]);
        } else {
            float rq = 1.f / (1.f + __expf(-bq));   // sigmoid of my owned b
            #pragma unroll
            for (int tt = 0; tt < 4; tt++) {
                float s = 0.f;
                #pragma unroll
                for (int o = 0; o < 4; o++) {
                    float r = __shfl_sync(FULL, rq, (lane & 16) | (o*4 + tt));
                    s = fmaf(uh[o*4 + tt], r, s);
                }
                pt[tt] = s;
            }
        }
        // segmented 16-lane norms: pos lanes need max|p|, app lanes need sum p^2
        #pragma unroll
        for (int tt = 0; tt < 4; tt++) {
            float x = app ? pt[tt]*pt[tt] : fabsf(pt[tt]);
            #pragma unroll
            for (int d = 1; d < 16; d <<= 1) {
                float y = __shfl_xor_sync(FULL, x, d);
                x = app ? (x + y) : fmaxf(x, y);
            }
            if (app) {
                v_[tt] = x / (1.f + x) * pt[tt] * rsqrtf(x + 1e-9f);
            } else {
                v_[tt] = pt[tt] / x;
            }
        }
        if (iter == 2) break;

        // multi-value butterfly: R_q = sum over own 16-half of uh[q]*v_[q&3];
        // result for q = lane&15 lands on this lane. 15 shfl total.
        float t8[8];
        #pragma unroll
        for (int j = 0; j < 8; j++) {
            float sa = uh[2*j]     * v_[(2*j)     & 3];
            float sb = uh[2*j + 1] * v_[(2*j + 1) & 3];
            float keep = b0 ? sb : sa;
            float send = b0 ? sa : sb;
            t8[j] = keep + __shfl_xor_sync(FULL, send, 1);
        }
        float t4[4];
        #pragma unroll
        for (int j = 0; j < 4; j++) {
            float keep = b1 ? t8[2*j + 1] : t8[2*j];
            float send = b1 ? t8[2*j]     : t8[2*j + 1];
            t4[j] = keep + __shfl_xor_sync(FULL, send, 2);
        }
        float t2[2];
        #pragma unroll
        for (int j = 0; j < 2; j++) {
            float keep = b2 ? t4[2*j + 1] : t4[2*j];
            float send = b2 ? t4[2*j]     : t4[2*j + 1];
            t2[j] = keep + __shfl_xor_sync(FULL, send, 4);
        }
        {
            float keep = b3 ? t2[1] : t2[0];
            float send = b3 ? t2[0] : t2[1];
            float R = keep + __shfl_xor_sync(FULL, send, 8);
            float other = __shfl_xor_sync(FULL, R, 16);   // cross pos/app halves
            bq = fmaf(R, other, bq);
        }
    }

    // ---- direct writeout: out[n, (half*4+tt)*32 + z, hh, gw] ----
    float* ob = out + (n*256 + (half*4)*32 + lane)*(HD*WD) + hh*WD + gw;
    #pragma unroll
    for (int tt = 0; tt < 4; tt++)
        ob[tt*32*(HD*WD)] = v_[tt];
}

extern "C" void kernel_launch(void* const* d_in, const int* in_sizes, int n_in,
                              void* d_out, int out_size)
{
    const float* inp = (const float*)d_in[0];   // (4,4,32,96,96)
    const float* Wc  = (const float*)d_in[1];   // (4,5,5,1,8)
    const float* Wp  = (const float*)d_in[2];   // (4,16,8)
    const float* Wa  = (const float*)d_in[3];   // (4,16,8)
    const float* ba  = (const float*)d_in[4];   // (4,8)
    float* out = (float*)d_out;                 // (4,8,32,96,96)

    const int smem_bytes = SMEM_F * (int)sizeof(float);
    cudaFuncSetAttribute(caps2d_fused_kernel,
                         cudaFuncAttributeMaxDynamicSharedMemorySize, smem_bytes);

    dim3 grid(WD / PXB, HD, 4);   // (12, 96, 4)
    dim3 block(512);
    caps2d_fused_kernel<<<grid, block, smem_bytes>>>(inp, Wc, Wp, Wa, ba, out);
}

// round 6
// speedup vs baseline: 2.6194x; 1.0066x over previous
#include <cuda_runtime.h>
#include <math.h>

// Problem constants
#define HD   96
#define WD   96
// tile
#define PXB  6      // pixels (w) per block
#define XCOLS 10    // PXB + 4 halo

// shared layout (floats)
#define IN_CH_STRIDE 51              // 5*10 + 1 pad (odd -> conflict-free lane stride)
#define IN_SH_F   (128*IN_CH_STRIDE) // 6528
#define CONV_SH_F (PXB*32*36)        // 6912 : conv[p][o*8+j][z], col-stride 36 (16B aligned)
#define WC_SH_F   800                // [o][ky][kx][j]
#define MP_SH_F   512                // [o][t][bb][k]  (k contiguous -> LDS.128)
#define MA_PAD    16                 // 64B shift: pos/app phase-2 loads hit disjoint banks
#define MA_SH_F   512
#define MB_SH_F   128                // b_app * sum_k m_app  per (o,t,bb)
#define SMEM_F (IN_SH_F + CONV_SH_F + WC_SH_F + MP_SH_F + MA_PAD + MA_SH_F + MB_SH_F)

__global__ void __launch_bounds__(384, 3)
caps2d_fused_kernel(const float* __restrict__ inp,
                    const float* __restrict__ Wc,
                    const float* __restrict__ Wp,
                    const float* __restrict__ Wa,
                    const float* __restrict__ ba,
                    float* __restrict__ out)
{
    extern __shared__ float smem[];
    float* in_sh   = smem;
    float* conv_sh = in_sh + IN_SH_F;
    float* wc_sh   = conv_sh + CONV_SH_F;
    float* mp_sh   = wc_sh + WC_SH_F;
    float* ma_sh   = mp_sh + MP_SH_F + MA_PAD;
    float* mb_sh   = ma_sh + MA_SH_F;

    const int tid  = threadIdx.x;
    const int warp = tid >> 5;
    const int lane = tid & 31;
    const int w0   = blockIdx.x * PXB;
    const int hh   = blockIdx.y;
    const int n    = blockIdx.z;

    // ---- load conv weights [o][tap][j] (natural layout) ----
    for (int e = tid; e < 800; e += 384) wc_sh[e] = Wc[e];

    // ---- load + relayout pose/app matrices: dst [o][t][bb][k] ----
    for (int e = tid; e < 512; e += 384) {
        int q8 = e >> 4;             // o*8 + t
        int bb = (e >> 2) & 3;
        int k  = e & 3;
        int o  = q8 >> 3, t = q8 & 7;
        int src = o*128 + t*16 + k*4 + bb;
        // column norm of W_pos[o] over k (axis=-2) for fixed (t,bb)
        float s = 0.f;
        #pragma unroll
        for (int kk = 0; kk < 4; kk++) {
            float v = Wp[o*128 + t*16 + kk*4 + bb];
            s += v * v;
        }
        float nrm = sqrtf(fmaxf(s, 1e-12f));
        mp_sh[e] = Wp[src] / nrm;
        ma_sh[e] = Wa[src];
    }
    // ---- precompute folded app bias: mb[(o*8+t)*4+bb] = ba[o,t] * sum_k Wa[o,t,k,bb] ----
    if (tid < 128) {
        int bb = tid & 3, t = (tid >> 2) & 7, o = tid >> 5;
        float sm = 0.f;
        #pragma unroll
        for (int k = 0; k < 4; k++) sm += Wa[o*128 + t*16 + k*4 + bb];
        mb_sh[tid] = ba[o*8 + t] * sm;
    }

    // ---- load input halo tile, division-free: 64-thr groups own fixed (y,x), walk ch ----
    {
        int id  = tid & 63;          // 64 threads cover 50 (y,x) slots
        int y   = id / 10;
        int x   = id - y * 10;
        int ch0 = tid >> 6;          // 0..5 ; ch = ch0 + 6*c
        int gy  = hh + y - 2;
        int gx  = w0 + x - 2;
        bool ok = (id < 50) && (gy >= 0) && (gy < HD) && (gx >= 0) && (gx < WD);
        const float* src = inp + ((n*128 + ch0)*HD + gy)*WD + gx;
        float* dst = in_sh + ch0*IN_CH_STRIDE + y*XCOLS + x;
        #pragma unroll
        for (int c = 0; c < 22; c++) {
            int ch = ch0 + 6*c;
            if (id < 50 && ch < 128) dst[0] = ok ? src[0] : 0.f;
            src += 6*HD*WD;
            dst += 6*IN_CH_STRIDE;
        }
    }
    __syncthreads();

    // ---- phase 1: depthwise 5x5 conv. warp = (o = warp&3, pixel pair pg = warp>>2) ----
    {
        const int o  = warp & 3;
        const int p0 = (warp >> 2) * 2;
        float acc[16];               // [px2][j=8]
        #pragma unroll
        for (int q = 0; q < 16; q++) acc[q] = 0.f;
        const float* ib  = in_sh + (o*32 + lane)*IN_CH_STRIDE;
        const float* wcb = wc_sh + o*200;
        #pragma unroll
        for (int ky = 0; ky < 5; ky++) {
            float r[6];
            #pragma unroll
            for (int q = 0; q < 6; q++) r[q] = ib[ky*XCOLS + p0 + q];
            #pragma unroll
            for (int kx = 0; kx < 5; kx++) {
                const float4 wa = *reinterpret_cast<const float4*>(wcb + (ky*5 + kx)*8);
                const float4 wb = *reinterpret_cast<const float4*>(wcb + (ky*5 + kx)*8 + 4);
                const float va = r[kx];
                const float vb = r[kx + 1];
                acc[0] = fmaf(va, wa.x, acc[0]);
                acc[1] = fmaf(va, wa.y, acc[1]);
                acc[2] = fmaf(va, wa.z, acc[2]);
                acc[3] = fmaf(va, wa.w, acc[3]);
                acc[4] = fmaf(va, wb.x, acc[4]);
                acc[5] = fmaf(va, wb.y, acc[5]);
                acc[6] = fmaf(va, wb.z, acc[6]);
                acc[7] = fmaf(va, wb.w, acc[7]);
                acc[8]  = fmaf(vb, wa.x, acc[8]);
                acc[9]  = fmaf(vb, wa.y, acc[9]);
                acc[10] = fmaf(vb, wa.z, acc[10]);
                acc[11] = fmaf(vb, wa.w, acc[11]);
                acc[12] = fmaf(vb, wb.x, acc[12]);
                acc[13] = fmaf(vb, wb.y, acc[13]);
                acc[14] = fmaf(vb, wb.z, acc[14]);
                acc[15] = fmaf(vb, wb.w, acc[15]);
            }
        }
        float* c0 = conv_sh + p0*(32*36)       + (o*8)*36 + lane;
        float* c1 = conv_sh + (p0 + 1)*(32*36) + (o*8)*36 + lane;
        #pragma unroll
        for (int j = 0; j < 8; j++) {
            c0[j*36] = acc[j];
            c1[j*36] = acc[8 + j];
        }
    }
    __syncthreads();   // role swap: conv (o,pg) -> routing (pixel, t-half)

    const int half = warp & 1;         // t half: 0 -> t 0..3, 1 -> t 4..7
    const int p    = warp >> 1;        // pixel within tile
    const int gw   = w0 + p;
    const int a_   = (lane >> 2) & 3;  // pose/app matrix row
    const int bb   = lane & 3;         // pose/app matrix col
    const bool app = (lane >> 4) != 0; // 0 = pos half (z<16), 1 = app half
    float* csh = conv_sh + p * (32*36);

    const float cy = (float)hh * (1.f/96.f);
    const float cx = (float)gw * (1.f/96.f);

    // ---- phase 2: u_hat[z=lane][q = o*4+tt], this half's 4 t values ----
    float uh[16];
    #pragma unroll
    for (int o = 0; o < 4; o++) {
        #pragma unroll
        for (int tt = 0; tt < 4; tt++) {
            const int t  = half*4 + tt;
            const int j  = (app ? 4 : 0) + (t >> 1);     // conv filter column
            const int zb = ((t & 1) << 4) + (a_ << 2);
            const float4 cv = *reinterpret_cast<const float4*>(csh + (o*8 + j)*36 + zb);
            const float* msrc = (app ? ma_sh : mp_sh) + ((o*8 + t)*4 + bb)*4;
            float4 m = *reinterpret_cast<const float4*>(msrc);
            float s0 = 0.f;
            if (app) {
                s0 = mb_sh[(o*8 + t)*4 + bb];
            } else {
                if (bb == 0)      m.w += cx;
                else if (bb == 1) m.w += cy;
            }
            float s;
            s = fmaf(cv.x, m.x, s0);
            s = fmaf(cv.y, m.y, s);
            s = fmaf(cv.z, m.z, s);
            s = fmaf(cv.w, m.w, s);
            uh[o*4 + tt] = s;
        }
    }

    // ---- phase 3: dynamic routing, b distributed (lane q = lane&15 owns b_q) ----
    const unsigned FULL = 0xffffffffu;
    const bool b0 = (lane & 1) != 0;
    const bool b1 = (lane & 2) != 0;
    const bool b2 = (lane & 4) != 0;
    const bool b3 = (lane & 8) != 0;
    float bq = 0.f;
    float v_[4];

    for (int iter = 0; iter < 3; iter++) {
        // p[tt] = sum_o uh[o*4+tt] * sigmoid(b[o*4+tt])
        float pt[4];
        if (iter == 0) {
            #pragma unroll
            for (int tt = 0; tt < 4; tt++)
                pt[tt] = 0.5f * (uh[tt] + uh[4 + tt] + uh[8 + tt] + uh[12 + tt]);
        } else {
            float rq = 1.f / (1.f + __expf(-bq));   // sigmoid of my owned b
            #pragma unroll
            for (int tt = 0; tt < 4; tt++) {
                float s = 0.f;
                #pragma unroll
                for (int o = 0; o < 4; o++) {
                    float r = __shfl_sync(FULL, rq, (lane & 16) | (o*4 + tt));
                    s = fmaf(uh[o*4 + tt], r, s);
                }
                pt[tt] = s;
            }
        }
        // segmented 16-lane norms: pos lanes need max|p|, app lanes need sum p^2
        #pragma unroll
        for (int tt = 0; tt < 4; tt++) {
            float x = app ? pt[tt]*pt[tt] : fabsf(pt[tt]);
            #pragma unroll
            for (int d = 1; d < 16; d <<= 1) {
                float y = __shfl_xor_sync(FULL, x, d);
                x = app ? (x + y) : fmaxf(x, y);
            }
            if (app) {
                v_[tt] = x / (1.f + x) * pt[tt] * rsqrtf(x + 1e-9f);
            } else {
                v_[tt] = pt[tt] / x;
            }
        }
        if (iter == 2) break;

        // multi-value butterfly: R_q = sum over own 16-half of uh[q]*v_[q&3];
        // result for q = lane&15 lands on this lane. 15 shfl total.
        float t8[8];
        #pragma unroll
        for (int j = 0; j < 8; j++) {
            float sa = uh[2*j]     * v_[(2*j)     & 3];
            float sb = uh[2*j + 1] * v_[(2*j + 1) & 3];
            float keep = b0 ? sb : sa;
            float send = b0 ? sa : sb;
            t8[j] = keep + __shfl_xor_sync(FULL, send, 1);
        }
        float t4[4];
        #pragma unroll
        for (int j = 0; j < 4; j++) {
            float keep = b1 ? t8[2*j + 1] : t8[2*j];
            float send = b1 ? t8[2*j]     : t8[2*j + 1];
            t4[j] = keep + __shfl_xor_sync(FULL, send, 2);
        }
        float t2[2];
        #pragma unroll
        for (int j = 0; j < 2; j++) {
            float keep = b2 ? t4[2*j + 1] : t4[2*j];
            float send = b2 ? t4[2*j]     : t4[2*j + 1];
            t2[j] = keep + __shfl_xor_sync(FULL, send, 4);
        }
        {
            float keep = b3 ? t2[1] : t2[0];
            float send = b3 ? t2[0] : t2[1];
            float R = keep + __shfl_xor_sync(FULL, send, 8);
            float other = __shfl_xor_sync(FULL, R, 16);   // cross pos/app halves
            bq = fmaf(R, other, bq);
        }
    }

    // ---- direct writeout: out[n, (half*4+tt)*32 + z, hh, gw] ----
    float* ob = out + (n*256 + (half*4)*32 + lane)*(HD*WD) + hh*WD + gw;
    #pragma unroll
    for (int tt = 0; tt < 4; tt++)
        ob[tt*32*(HD*WD)] = v_[tt];
}

extern "C" void kernel_launch(void* const* d_in, const int* in_sizes, int n_in,
                              void* d_out, int out_size)
{
    const float* inp = (const float*)d_in[0];   // (4,4,32,96,96)
    const float* Wc  = (const float*)d_in[1];   // (4,5,5,1,8)
    const float* Wp  = (const float*)d_in[2];   // (4,16,8)
    const float* Wa  = (const float*)d_in[3];   // (4,16,8)
    const float* ba  = (const float*)d_in[4];   // (4,8)
    float* out = (float*)d_out;                 // (4,8,32,96,96)

    const int smem_bytes = SMEM_F * (int)sizeof(float);
    cudaFuncSetAttribute(caps2d_fused_kernel,
                         cudaFuncAttributeMaxDynamicSharedMemorySize, smem_bytes);

    dim3 grid(WD / PXB, HD, 4);   // (16, 96, 4)
    dim3 block(384);
    caps2d_fused_kernel<<<grid, block, smem_bytes>>>(inp, Wc, Wp, Wa, ba, out);
}

// round 7
// speedup vs baseline: 3.5212x; 1.3443x over previous
#include <cuda_runtime.h>
#include <math.h>

// Problem constants
#define HD   96
#define WD   96
// tile
#define PXB  8      // pixels (w) per block
#define ROWS 4      // output rows per block
#define XW   16     // halo window cols [w0-4, w0+12), 4-aligned
#define CHS  129    // channel stride in floats: 8 rows * 16 + 1 (odd -> conflict-free)

// shared layout (floats)
#define IN_SH_F   (128*CHS)          // 16512
#define CONV_SH_F (PXB*32*36)        // 9216 : conv[p][o*8+j][z] ; reused as out staging 256x9
#define WC_SH_F   800                // [o][ky][kx][j]
#define MP_SH_F   512                // [o][t][bb][k]  (k contiguous -> LDS.128)
#define MA_PAD    16
#define MA_SH_F   512
#define MB_SH_F   128                // b_app * sum_k m_app  per (o,t,bb)
#define SMEM_F (IN_SH_F + CONV_SH_F + WC_SH_F + MP_SH_F + MA_PAD + MA_SH_F + MB_SH_F)

__global__ void __launch_bounds__(512, 2)
caps2d_fused_kernel(const float* __restrict__ inp,
                    const float* __restrict__ Wc,
                    const float* __restrict__ Wp,
                    const float* __restrict__ Wa,
                    const float* __restrict__ ba,
                    float* __restrict__ out)
{
    extern __shared__ float smem[];
    float* in_sh   = smem;
    float* conv_sh = in_sh + IN_SH_F;
    float* wc_sh   = conv_sh + CONV_SH_F;
    float* mp_sh   = wc_sh + WC_SH_F;
    float* ma_sh   = mp_sh + MP_SH_F + MA_PAD;
    float* mb_sh   = ma_sh + MA_SH_F;

    const int tid  = threadIdx.x;
    const int warp = tid >> 5;
    const int lane = tid & 31;
    const int w0   = blockIdx.x * PXB;
    const int hh0  = blockIdx.y * ROWS;
    const int n    = blockIdx.z;

    // ---- load conv weights [o][tap][j] (natural layout) ----
    for (int e = tid; e < 800; e += 512) wc_sh[e] = Wc[e];

    // ---- load + relayout pose/app matrices: dst [o][t][bb][k] ----
    {
        int e  = tid;
        int q8 = e >> 4;             // o*8 + t
        int bb = (e >> 2) & 3;
        int k  = e & 3;
        int o  = q8 >> 3, t = q8 & 7;
        int src = o*128 + t*16 + k*4 + bb;
        float s = 0.f;
        #pragma unroll
        for (int kk = 0; kk < 4; kk++) {
            float v = Wp[o*128 + t*16 + kk*4 + bb];
            s += v * v;
        }
        float nrm = sqrtf(fmaxf(s, 1e-12f));
        mp_sh[e] = Wp[src] / nrm;
        ma_sh[e] = Wa[src];
    }
    // ---- folded app bias: mb[(o*8+t)*4+bb] = ba[o,t] * sum_k Wa[o,t,k,bb] ----
    if (tid < 128) {
        int bb = tid & 3, t = (tid >> 2) & 7, o = tid >> 5;
        float sm = 0.f;
        #pragma unroll
        for (int k = 0; k < 4; k++) sm += Wa[o*128 + t*16 + k*4 + bb];
        mb_sh[tid] = ba[o*8 + t] * sm;
    }

    // ---- vector halo load: 8 rows x 16 cols x 128 ch ----
    // window col c <-> gx = w0-4+c ; each float4 group fully valid or fully OOB
    {
        int id  = tid & 31;          // (y,g)
        int y   = id >> 2;           // 0..7
        int g   = id & 3;            // float4 group
        int ch0 = tid >> 5;          // 0..15 ; ch = ch0 + 16*c
        int gy  = hh0 - 2 + y;
        int gx0 = w0 - 4 + g*4;
        bool ok = (gy >= 0) && (gy < HD) && (gx0 >= 0) && (gx0 + 3 < WD);
        const float* src = inp + ((n*128 + ch0)*HD + gy)*WD + gx0;
        float* dst = in_sh + ch0*CHS + y*XW + g*4;
        #pragma unroll
        for (int c = 0; c < 8; c++) {
            float4 v = make_float4(0.f, 0.f, 0.f, 0.f);
            if (ok) v = *reinterpret_cast<const float4*>(src);
            dst[0] = v.x; dst[1] = v.y; dst[2] = v.z; dst[3] = v.w;
            src += 16*HD*WD;
            dst += 16*CHS;
        }
    }
    __syncthreads();

    // routing-role constants
    const int half = warp & 1;         // t half: 0 -> t 0..3, 1 -> t 4..7
    const int p    = warp >> 1;        // pixel within tile
    const int gw   = w0 + p;
    const int a_   = (lane >> 2) & 3;
    const int bb   = lane & 3;
    const bool app = (lane >> 4) != 0;
    const float cx = (float)gw * (1.f/96.f);
    // conv-role constants
    const int o_c  = warp & 3;
    const int p0   = (warp >> 2) * 2;
    const unsigned FULL = 0xffffffffu;
    const bool x0 = (lane & 1) != 0;
    const bool x1 = (lane & 2) != 0;
    const bool x2 = (lane & 4) != 0;
    const bool x3 = (lane & 8) != 0;

    for (int hr = 0; hr < ROWS; hr++) {
        // ---- phase 1: depthwise 5x5 conv. warp = (o_c, pixel pair p0) ----
        {
            float acc[16];
            #pragma unroll
            for (int q = 0; q < 16; q++) acc[q] = 0.f;
            const float* ib  = in_sh + (o_c*32 + lane)*CHS;
            const float* wcb = wc_sh + o_c*200;
            #pragma unroll
            for (int ky = 0; ky < 5; ky++) {
                float r[6];
                #pragma unroll
                for (int q = 0; q < 6; q++) r[q] = ib[(hr + ky)*XW + p0 + 2 + q];
                #pragma unroll
                for (int kx = 0; kx < 5; kx++) {
                    const float4 wa = *reinterpret_cast<const float4*>(wcb + (ky*5 + kx)*8);
                    const float4 wb = *reinterpret_cast<const float4*>(wcb + (ky*5 + kx)*8 + 4);
                    const float va = r[kx];
                    const float vb = r[kx + 1];
                    acc[0] = fmaf(va, wa.x, acc[0]);
                    acc[1] = fmaf(va, wa.y, acc[1]);
                    acc[2] = fmaf(va, wa.z, acc[2]);
                    acc[3] = fmaf(va, wa.w, acc[3]);
                    acc[4] = fmaf(va, wb.x, acc[4]);
                    acc[5] = fmaf(va, wb.y, acc[5]);
                    acc[6] = fmaf(va, wb.z, acc[6]);
                    acc[7] = fmaf(va, wb.w, acc[7]);
                    acc[8]  = fmaf(vb, wa.x, acc[8]);
                    acc[9]  = fmaf(vb, wa.y, acc[9]);
                    acc[10] = fmaf(vb, wa.z, acc[10]);
                    acc[11] = fmaf(vb, wa.w, acc[11]);
                    acc[12] = fmaf(vb, wb.x, acc[12]);
                    acc[13] = fmaf(vb, wb.y, acc[13]);
                    acc[14] = fmaf(vb, wb.z, acc[14]);
                    acc[15] = fmaf(vb, wb.w, acc[15]);
                }
            }
            float* c0 = conv_sh + p0*(32*36)       + (o_c*8)*36 + lane;
            float* c1 = conv_sh + (p0 + 1)*(32*36) + (o_c*8)*36 + lane;
            #pragma unroll
            for (int j = 0; j < 8; j++) {
                c0[j*36] = acc[j];
                c1[j*36] = acc[8 + j];
            }
        }
        __syncthreads();   // conv_sh ready; role swap

        // ---- phase 2: u_hat[z=lane][q = o*4+tt] ----
        const float cy = (float)(hh0 + hr) * (1.f/96.f);
        float* csh = conv_sh + p * (32*36);
        float uh[16];
        #pragma unroll
        for (int o = 0; o < 4; o++) {
            #pragma unroll
            for (int tt = 0; tt < 4; tt++) {
                const int t  = half*4 + tt;
                const int j  = (app ? 4 : 0) + (t >> 1);
                const int zb = ((t & 1) << 4) + (a_ << 2);
                const float4 cv = *reinterpret_cast<const float4*>(csh + (o*8 + j)*36 + zb);
                const float* msrc = (app ? ma_sh : mp_sh) + ((o*8 + t)*4 + bb)*4;
                float4 m = *reinterpret_cast<const float4*>(msrc);
                float s0 = 0.f;
                if (app) {
                    s0 = mb_sh[(o*8 + t)*4 + bb];
                } else {
                    if (bb == 0)      m.w += cx;
                    else if (bb == 1) m.w += cy;
                }
                float s;
                s = fmaf(cv.x, m.x, s0);
                s = fmaf(cv.y, m.y, s);
                s = fmaf(cv.z, m.z, s);
                s = fmaf(cv.w, m.w, s);
                uh[o*4 + tt] = s;
            }
        }

        // ---- phase 3: dynamic routing ----
        float bq = 0.f;
        float v_[4];
        for (int iter = 0; iter < 3; iter++) {
            float pt[4];
            if (iter == 0) {
                #pragma unroll
                for (int tt = 0; tt < 4; tt++)
                    pt[tt] = 0.5f * (uh[tt] + uh[4 + tt] + uh[8 + tt] + uh[12 + tt]);
            } else {
                float rq = 1.f / (1.f + __expf(-bq));
                #pragma unroll
                for (int tt = 0; tt < 4; tt++) {
                    float s = 0.f;
                    #pragma unroll
                    for (int o = 0; o < 4; o++) {
                        float r = __shfl_sync(FULL, rq, (lane & 16) | (o*4 + tt));
                        s = fmaf(uh[o*4 + tt], r, s);
                    }
                    pt[tt] = s;
                }
            }
            #pragma unroll
            for (int tt = 0; tt < 4; tt++) {
                float x = app ? pt[tt]*pt[tt] : fabsf(pt[tt]);
                #pragma unroll
                for (int d = 1; d < 16; d <<= 1) {
                    float y = __shfl_xor_sync(FULL, x, d);
                    x = app ? (x + y) : fmaxf(x, y);
                }
                if (app) {
                    v_[tt] = x / (1.f + x) * pt[tt] * rsqrtf(x + 1e-9f);
                } else {
                    v_[tt] = pt[tt] / x;
                }
            }
            if (iter == 2) break;

            // multi-value butterfly, 15+1 shfl
            float t8[8];
            #pragma unroll
            for (int j = 0; j < 8; j++) {
                float sa = uh[2*j]     * v_[(2*j)     & 3];
                float sb = uh[2*j + 1] * v_[(2*j + 1) & 3];
                float keep = x0 ? sb : sa;
                float send = x0 ? sa : sb;
                t8[j] = keep + __shfl_xor_sync(FULL, send, 1);
            }
            float t4[4];
            #pragma unroll
            for (int j = 0; j < 4; j++) {
                float keep = x1 ? t8[2*j + 1] : t8[2*j];
                float send = x1 ? t8[2*j]     : t8[2*j + 1];
                t4[j] = keep + __shfl_xor_sync(FULL, send, 2);
            }
            float t2[2];
            #pragma unroll
            for (int j = 0; j < 2; j++) {
                float keep = x2 ? t4[2*j + 1] : t4[2*j];
                float send = x2 ? t4[2*j]     : t4[2*j + 1];
                t2[j] = keep + __shfl_xor_sync(FULL, send, 4);
            }
            {
                float keep = x3 ? t2[1] : t2[0];
                float send = x3 ? t2[0] : t2[1];
                float R = keep + __shfl_xor_sync(FULL, send, 8);
                float other = __shfl_xor_sync(FULL, R, 16);
                bq = fmaf(R, other, bq);
            }
        }

        __syncthreads();   // all conv_sh reads done -> reuse as out staging

        // ---- stage: os[row][px], row = (half*4+tt)*32+lane, stride 9 ----
        #pragma unroll
        for (int tt = 0; tt < 4; tt++)
            conv_sh[((half*4 + tt)*32 + lane)*9 + p] = v_[tt];
        __syncthreads();

        // ---- coalesced writeout: warp covers 4 rows x 8 px -> 4 sectors/STG ----
        {
            int x  = tid & 7;
            int r0 = tid >> 3;      // 0..63
            const float* os = conv_sh;
            float* ob = out + n*256*(HD*WD) + (hh0 + hr)*WD + w0 + x;
            #pragma unroll
            for (int k = 0; k < 4; k++) {
                int row = r0 + 64*k;
                ob[row*(HD*WD)] = os[row*9 + x];
            }
        }
        __syncthreads();   // writeout reads done before next row's conv overwrites
    }
}

extern "C" void kernel_launch(void* const* d_in, const int* in_sizes, int n_in,
                              void* d_out, int out_size)
{
    const float* inp = (const float*)d_in[0];   // (4,4,32,96,96)
    const float* Wc  = (const float*)d_in[1];   // (4,5,5,1,8)
    const float* Wp  = (const float*)d_in[2];   // (4,16,8)
    const float* Wa  = (const float*)d_in[3];   // (4,16,8)
    const float* ba  = (const float*)d_in[4];   // (4,8)
    float* out = (float*)d_out;                 // (4,8,32,96,96)

    const int smem_bytes = SMEM_F * (int)sizeof(float);
    cudaFuncSetAttribute(caps2d_fused_kernel,
                         cudaFuncAttributeMaxDynamicSharedMemorySize, smem_bytes);

    dim3 grid(WD / PXB, HD / ROWS, 4);   // (12, 24, 4)
    dim3 block(512);
    caps2d_fused_kernel<<<grid, block, smem_bytes>>>(inp, Wc, Wp, Wa, ba, out);
}

// round 9
// speedup vs baseline: 3.5585x; 1.0106x over previous
#include <cuda_runtime.h>
#include <math.h>
#include <cstdint>

// Problem constants
#define HD   96
#define WD   96
// tile
#define PXB  8      // pixels (w) per block
#define ROWS 4      // output rows per block
#define XW   16     // halo window cols [w0-4, w0+12), 4-aligned
#define CHS  129    // channel stride in floats: 8 rows * 16 + 1 (odd -> conflict-free)

// shared layout (floats)
#define IN_SH_F   (128*CHS)          // 16512
#define CONV_SH_F (PXB*32*36)        // 9216 : conv[p][o*8+j][z] ; reused as out staging 256x9
#define WC_SH_F   800                // [o][ky][kx][j]
#define MP_SH_F   512                // [o][t][bb][k]  (k contiguous -> LDS.128)
#define MA_PAD    16
#define MA_SH_F   512
#define MB_SH_F   128                // b_app * sum_k m_app  per (o,t,bb)
#define SMEM_F (IN_SH_F + CONV_SH_F + WC_SH_F + MP_SH_F + MA_PAD + MA_SH_F + MB_SH_F)

// Blackwell packed fp32 ops (b64 register pairs)
#define FMA_F32X2(d, a, b, c) \
    asm("fma.rn.f32x2 %0, %1, %2, %3;" : "=l"(d) : "l"(a), "l"(b), "l"(c))
#define PACK_DUP_F32X2(d, v) \
    asm("mov.b64 %0, {%1, %1};" : "=l"(d) : "f"(v))
#define UNPACK_F32X2(lo, hi, in) \
    asm("mov.b64 {%0, %1}, %2;" : "=f"(lo), "=f"(hi) : "l"(in))

__global__ void __launch_bounds__(512, 2)
caps2d_fused_kernel(const float* __restrict__ inp,
                    const float* __restrict__ Wc,
                    const float* __restrict__ Wp,
                    const float* __restrict__ Wa,
                    const float* __restrict__ ba,
                    float* __restrict__ out)
{
    extern __shared__ float smem[];
    float* in_sh   = smem;
    float* conv_sh = in_sh + IN_SH_F;
    float* wc_sh   = conv_sh + CONV_SH_F;
    float* mp_sh   = wc_sh + WC_SH_F;
    float* ma_sh   = mp_sh + MP_SH_F + MA_PAD;
    float* mb_sh   = ma_sh + MA_SH_F;

    const int tid  = threadIdx.x;
    const int warp = tid >> 5;
    const int lane = tid & 31;
    const int w0   = blockIdx.x * PXB;
    const int hh0  = blockIdx.y * ROWS;
    const int n    = blockIdx.z;

    // ---- load conv weights [o][tap][j] (natural layout) ----
    for (int e = tid; e < 800; e += 512) wc_sh[e] = Wc[e];

    // ---- load + relayout pose/app matrices: dst [o][t][bb][k] ----
    {
        int e  = tid;
        int q8 = e >> 4;             // o*8 + t
        int bb = (e >> 2) & 3;
        int k  = e & 3;
        int o  = q8 >> 3, t = q8 & 7;
        int src = o*128 + t*16 + k*4 + bb;
        float s = 0.f;
        #pragma unroll
        for (int kk = 0; kk < 4; kk++) {
            float v = Wp[o*128 + t*16 + kk*4 + bb];
            s += v * v;
        }
        float nrm = sqrtf(fmaxf(s, 1e-12f));
        mp_sh[e] = Wp[src] / nrm;
        ma_sh[e] = Wa[src];
    }
    // ---- folded app bias: mb[(o*8+t)*4+bb] = ba[o,t] * sum_k Wa[o,t,k,bb] ----
    if (tid < 128) {
        int bb = tid & 3, t = (tid >> 2) & 7, o = tid >> 5;
        float sm = 0.f;
        #pragma unroll
        for (int k = 0; k < 4; k++) sm += Wa[o*128 + t*16 + k*4 + bb];
        mb_sh[tid] = ba[o*8 + t] * sm;
    }

    // ---- vector halo load: 8 rows x 16 cols x 128 ch ----
    {
        int id  = tid & 31;          // (y,g)
        int y   = id >> 2;           // 0..7
        int g   = id & 3;            // float4 group
        int ch0 = tid >> 5;          // 0..15 ; ch = ch0 + 16*c
        int gy  = hh0 - 2 + y;
        int gx0 = w0 - 4 + g*4;
        bool ok = (gy >= 0) && (gy < HD) && (gx0 >= 0) && (gx0 + 3 < WD);
        const float* src = inp + ((n*128 + ch0)*HD + gy)*WD + gx0;
        float* dst = in_sh + ch0*CHS + y*XW + g*4;
        #pragma unroll
        for (int c = 0; c < 8; c++) {
            float4 v = make_float4(0.f, 0.f, 0.f, 0.f);
            if (ok) v = *reinterpret_cast<const float4*>(src);
            dst[0] = v.x; dst[1] = v.y; dst[2] = v.z; dst[3] = v.w;
            src += 16*HD*WD;
            dst += 16*CHS;
        }
    }
    __syncthreads();

    // routing-role constants
    const int half = warp & 1;
    const int p    = warp >> 1;
    const int gw   = w0 + p;
    const int a_   = (lane >> 2) & 3;
    const int bb   = lane & 3;
    const bool app = (lane >> 4) != 0;
    const float cx = (float)gw * (1.f/96.f);
    // conv-role constants
    const int o_c  = warp & 3;
    const int p0   = (warp >> 2) * 2;
    const unsigned FULL = 0xffffffffu;
    const bool x0 = (lane & 1) != 0;
    const bool x1 = (lane & 2) != 0;
    const bool x2 = (lane & 4) != 0;
    const bool x3 = (lane & 8) != 0;

    for (int hr = 0; hr < ROWS; hr++) {
        // ---- phase 1: depthwise 5x5 conv, packed f32x2 (j-pairs) ----
        {
            uint64_t acc2[8];        // [px(2)][jpair(4)] : (j=2jp, j=2jp+1)
            #pragma unroll
            for (int q = 0; q < 8; q++) acc2[q] = 0ull;
            const float* ib  = in_sh + (o_c*32 + lane)*CHS;
            const float* wcb = wc_sh + o_c*200;
            #pragma unroll
            for (int ky = 0; ky < 5; ky++) {
                float r[6];
                #pragma unroll
                for (int q = 0; q < 6; q++) r[q] = ib[(hr + ky)*XW + p0 + 2 + q];
                #pragma unroll
                for (int kx = 0; kx < 5; kx++) {
                    // 16B weight load = 2 b64 j-pairs; second 16B = 2 more
                    const ulonglong2 wA = *reinterpret_cast<const ulonglong2*>(wcb + (ky*5 + kx)*8);
                    const ulonglong2 wB = *reinterpret_cast<const ulonglong2*>(wcb + (ky*5 + kx)*8 + 4);
                    uint64_t va2, vb2;
                    PACK_DUP_F32X2(va2, r[kx]);
                    PACK_DUP_F32X2(vb2, r[kx + 1]);
                    FMA_F32X2(acc2[0], va2, wA.x, acc2[0]);
                    FMA_F32X2(acc2[1], va2, wA.y, acc2[1]);
                    FMA_F32X2(acc2[2], va2, wB.x, acc2[2]);
                    FMA_F32X2(acc2[3], va2, wB.y, acc2[3]);
                    FMA_F32X2(acc2[4], vb2, wA.x, acc2[4]);
                    FMA_F32X2(acc2[5], vb2, wA.y, acc2[5]);
                    FMA_F32X2(acc2[6], vb2, wB.x, acc2[6]);
                    FMA_F32X2(acc2[7], vb2, wB.y, acc2[7]);
                }
            }
            float* c0 = conv_sh + p0*(32*36)       + (o_c*8)*36 + lane;
            float* c1 = conv_sh + (p0 + 1)*(32*36) + (o_c*8)*36 + lane;
            #pragma unroll
            for (int jp = 0; jp < 4; jp++) {
                float lo, hi;
                UNPACK_F32X2(lo, hi, acc2[jp]);
                c0[(2*jp)*36]     = lo;
                c0[(2*jp + 1)*36] = hi;
            }
            #pragma unroll
            for (int jp = 0; jp < 4; jp++) {
                float lo, hi;
                UNPACK_F32X2(lo, hi, acc2[4 + jp]);
                c1[(2*jp)*36]     = lo;
                c1[(2*jp + 1)*36] = hi;
            }
        }
        __syncthreads();   // conv_sh ready; role swap

        // ---- phase 2: u_hat[z=lane][q = o*4+tt] ----
        const float cy = (float)(hh0 + hr) * (1.f/96.f);
        float* csh = conv_sh + p * (32*36);
        float uh[16];
        #pragma unroll
        for (int o = 0; o < 4; o++) {
            #pragma unroll
            for (int tt = 0; tt < 4; tt++) {
                const int t  = half*4 + tt;
                const int j  = (app ? 4 : 0) + (t >> 1);
                const int zb = ((t & 1) << 4) + (a_ << 2);
                const float4 cv = *reinterpret_cast<const float4*>(csh + (o*8 + j)*36 + zb);
                const float* msrc = (app ? ma_sh : mp_sh) + ((o*8 + t)*4 + bb)*4;
                float4 m = *reinterpret_cast<const float4*>(msrc);
                float s0 = 0.f;
                if (app) {
                    s0 = mb_sh[(o*8 + t)*4 + bb];
                } else {
                    if (bb == 0)      m.w += cx;
                    else if (bb == 1) m.w += cy;
                }
                float s;
                s = fmaf(cv.x, m.x, s0);
                s = fmaf(cv.y, m.y, s);
                s = fmaf(cv.z, m.z, s);
                s = fmaf(cv.w, m.w, s);
                uh[o*4 + tt] = s;
            }
        }

        // ---- phase 3: dynamic routing ----
        float bq = 0.f;
        float v_[4];
        for (int iter = 0; iter < 3; iter++) {
            float pt[4];
            if (iter == 0) {
                #pragma unroll
                for (int tt = 0; tt < 4; tt++)
                    pt[tt] = 0.5f * (uh[tt] + uh[4 + tt] + uh[8 + tt] + uh[12 + tt]);
            } else {
                float rq = 1.f / (1.f + __expf(-bq));
                #pragma unroll
                for (int tt = 0; tt < 4; tt++) {
                    float s = 0.f;
                    #pragma unroll
                    for (int o = 0; o < 4; o++) {
                        float r = __shfl_sync(FULL, rq, (lane & 16) | (o*4 + tt));
                        s = fmaf(uh[o*4 + tt], r, s);
                    }
                    pt[tt] = s;
                }
            }
            #pragma unroll
            for (int tt = 0; tt < 4; tt++) {
                float x = app ? pt[tt]*pt[tt] : fabsf(pt[tt]);
                #pragma unroll
                for (int d = 1; d < 16; d <<= 1) {
                    float y = __shfl_xor_sync(FULL, x, d);
                    x = app ? (x + y) : fmaxf(x, y);
                }
                if (app) {
                    v_[tt] = x / (1.f + x) * pt[tt] * rsqrtf(x + 1e-9f);
                } else {
                    v_[tt] = pt[tt] / x;
                }
            }
            if (iter == 2) break;

            // multi-value butterfly, 15+1 shfl
            float t8[8];
            #pragma unroll
            for (int j = 0; j < 8; j++) {
                float sa = uh[2*j]     * v_[(2*j)     & 3];
                float sb = uh[2*j + 1] * v_[(2*j + 1) & 3];
                float keep = x0 ? sb : sa;
                float send = x0 ? sa : sb;
                t8[j] = keep + __shfl_xor_sync(FULL, send, 1);
            }
            float t4[4];
            #pragma unroll
            for (int j = 0; j < 4; j++) {
                float keep = x1 ? t8[2*j + 1] : t8[2*j];
                float send = x1 ? t8[2*j]     : t8[2*j + 1];
                t4[j] = keep + __shfl_xor_sync(FULL, send, 2);
            }
            float t2[2];
            #pragma unroll
            for (int j = 0; j < 2; j++) {
                float keep = x2 ? t4[2*j + 1] : t4[2*j];
                float send = x2 ? t4[2*j]     : t4[2*j + 1];
                t2[j] = keep + __shfl_xor_sync(FULL, send, 4);
            }
            {
                float keep = x3 ? t2[1] : t2[0];
                float send = x3 ? t2[0] : t2[1];
                float R = keep + __shfl_xor_sync(FULL, send, 8);
                float other = __shfl_xor_sync(FULL, R, 16);
                bq = fmaf(R, other, bq);
            }
        }

        __syncthreads();   // all conv_sh reads done -> reuse as out staging

        // ---- stage: os[row][px], row = (half*4+tt)*32+lane, stride 9 ----
        #pragma unroll
        for (int tt = 0; tt < 4; tt++)
            conv_sh[((half*4 + tt)*32 + lane)*9 + p] = v_[tt];
        __syncthreads();

        // ---- coalesced writeout: warp covers 4 rows x 8 px -> 4 sectors/STG ----
        {
            int x  = tid & 7;
            int r0 = tid >> 3;      // 0..63
            const float* os = conv_sh;
            float* ob = out + n*256*(HD*WD) + (hh0 + hr)*WD + w0 + x;
            #pragma unroll
            for (int k = 0; k < 4; k++) {
                int row = r0 + 64*k;
                ob[row*(HD*WD)] = os[row*9 + x];
            }
        }
        __syncthreads();   // writeout reads done before next row's conv overwrites
    }
}

extern "C" void kernel_launch(void* const* d_in, const int* in_sizes, int n_in,
                              void* d_out, int out_size)
{
    const float* inp = (const float*)d_in[0];   // (4,4,32,96,96)
    const float* Wc  = (const float*)d_in[1];   // (4,5,5,1,8)
    const float* Wp  = (const float*)d_in[2];   // (4,16,8)
    const float* Wa  = (const float*)d_in[3];   // (4,16,8)
    const float* ba  = (const float*)d_in[4];   // (4,8)
    float* out = (float*)d_out;                 // (4,8,32,96,96)

    const int smem_bytes = SMEM_F * (int)sizeof(float);
    cudaFuncSetAttribute(caps2d_fused_kernel,
                         cudaFuncAttributeMaxDynamicSharedMemorySize, smem_bytes);

    dim3 grid(WD / PXB, HD / ROWS, 4);   // (12, 24, 4)
    dim3 block(512);
    caps2d_fused_kernel<<<grid, block, smem_bytes>>>(inp, Wc, Wp, Wa, ba, out);
}